// round 8
// baseline (speedup 1.0000x reference)
#include <cuda_runtime.h>
#include <math.h>

#define NSEG    2047
#define NPTS    2048
#define NPIX    16384
#define NTILE   512          // 16 x-tiles (8px) * 32 y-tiles (4px)
#define NCAP    512          // smem candidate capacity
#define GAMMA_F 200.0f
#define STEPF   (2.0f / 127.0f)
// tile = 8x4 px, center (+3.5,+1.5): 2*half-diag = 2*sqrt(3.5^2+1.5^2) px
#define THR_ADD (7.615773f * STEPF + 1e-3f)
#define FINF    __int_as_float(0x7F800000)

__device__ __forceinline__ float satmul(float a, float b) {
    float r; asm("mul.rn.sat.f32 %0,%1,%2;" : "=f"(r) : "f"(a), "f"(b)); return r;
}

// Cross-CTA state, reset by the last loss-CTA every run (graph-replay safe).
__device__ float    g_pix[2][NPIX];
__device__ int      g_tile_cnt[NTILE];
__device__ float    g_loss = 0.0f;
__device__ unsigned g_done = 0;

// ---------------------------------------------------------------------------
// grid 1024 x 256: bid = w*512 + tile (8x4 px).
// Conv:   coalesced LDG.128 of raw coords (8 pts/thread), convert -> smem
//         float2 points + mask bytes.
// Phase1: 8 segs/thread from smem, eval at tile center, block-min U,
//         exact triangle-inequality cull; survivors -> s_seg/s_inv SoA.
// Phase2: thread = (pixel p=tid&31, slice h=tid>>5 of 8); streams s_seg
//         (warp-broadcast LDS), 2 accumulator chains.
// Pairing: g_pix publish, second arriver computes tile loss, 512th loss-CTA
//         writes out[0] and resets counters.
// ---------------------------------------------------------------------------
__global__ void __launch_bounds__(256, 6) fused_kernel(const float* __restrict__ pred,
                                                       const float* __restrict__ gt,
                                                       float* __restrict__ out) {
    const int tid  = threadIdx.x;
    const int bid  = blockIdx.x;
    const int w    = bid >> 9;
    const int tile = bid & (NTILE - 1);
    const int tx = tile & 15, ty = tile >> 4;

    const float* __restrict__ c = w ? gt : pred;

    const float cx = fmaf((float)(tx * 8) + 3.5f, STEPF, -1.0f);
    const float cy = fmaf((float)(ty * 4) + 1.5f, STEPF, -1.0f);

    const int p = tid & 31, h = tid >> 5;        // pixel, slice (8 warps)
    const int row = p >> 3, col = p & 7;
    const float gx = fmaf((float)(tx * 8 + col), STEPF, -1.0f);
    const float gy = fmaf((float)(ty * 4 + row), STEPF, -1.0f);

    __shared__ float2 s_pt[NPTS];                 // 16 KB converted points
    __shared__ unsigned char s_msk[NPTS];         //  2 KB segment-mask bytes
    __shared__ float4 s_seg[NCAP];                //  8 KB candidates
    __shared__ float  s_inv[NCAP];                //  2 KB
    __shared__ unsigned short s_ovf[NSEG - NCAP + 1];  // ~3 KB cold overflow
    __shared__ float  s_m[32][8];
    __shared__ float  s_red[8];
    __shared__ int    s_cnt;
    __shared__ int    s_flag;

    if (tid == 0) s_cnt = 0;

    // ---------------- Conv: coalesced load + convert into smem ----------------
    {
        // thread handles points [8*tid, 8*tid+8) = floats [24*tid, 24*tid+24)
        const float4* __restrict__ c4 = (const float4*)c;
        float f[24];
#pragma unroll
        for (int q = 0; q < 6; ++q) {
            const float4 v4 = __ldg(&c4[tid * 6 + q]);
            f[q * 4 + 0] = v4.x; f[q * 4 + 1] = v4.y;
            f[q * 4 + 2] = v4.z; f[q * 4 + 3] = v4.w;
        }
#pragma unroll
        for (int k = 0; k < 8; ++k) {
            const int pt = tid * 8 + k;
            const float x   = f[k * 3 + 0];
            const float y   = f[k * 3 + 1];
            const float pen = f[k * 3 + 2];
            s_pt[pt]  = make_float2(fmaf(x, 2.0f, -1.0f), fmaf(y, 2.0f, -1.0f));
            s_msk[pt] = w ? (pen != 0.0f) : (pen > 0.5f);
        }
    }
    __syncthreads();

    // ---------------- Phase 1: center eval + cull ----------------
    float d2c[8];
    float lmin = FINF;
#pragma unroll
    for (int k = 0; k < 8; ++k) {
        const int s = tid + (k << 8);
        float d2 = FINF;
        if (s < NSEG && !s_msk[s]) {
            const float2 pi = s_pt[s];
            const float2 pj = s_pt[s + 1];
            const float vx = pi.x - pj.x, vy = pi.y - pj.y;
            const float vn = vx * vx + vy * vy;
            const float inv = __fdividef(1.0f, vn);
            const float ux = cx - pj.x, uy = cy - pj.y;
            const float uv = fmaf(ux, vx, uy * vy);
            const float t  = satmul(uv, inv);       // NaN(0*inf) -> 0: exact for vn=0
            const float dx = fmaf(-t, vx, ux);
            const float dy = fmaf(-t, vy, uy);
            d2 = fmaf(dy, dy, dx * dx);
        }
        d2c[k] = d2;
        lmin = fminf(lmin, d2);
    }
#pragma unroll
    for (int o = 16; o > 0; o >>= 1)
        lmin = fminf(lmin, __shfl_xor_sync(0xFFFFFFFFu, lmin, o));
    if ((tid & 31) == 0) s_red[tid >> 5] = lmin;
    __syncthreads();
    float U = s_red[0];
#pragma unroll
    for (int q = 1; q < 8; ++q) U = fminf(U, s_red[q]);
    const float thd = sqrtf(U) + THR_ADD;
    const float thr = thd * thd;

#pragma unroll
    for (int k = 0; k < 8; ++k) {
        if (d2c[k] < thr) {
            const int s   = tid + (k << 8);
            const int pos = atomicAdd(&s_cnt, 1);
            if (pos < NCAP) {
                const float2 pi = s_pt[s];
                const float2 pj = s_pt[s + 1];
                const float vx = pi.x - pj.x, vy = pi.y - pj.y;
                const float vn = vx * vx + vy * vy;
                s_seg[pos] = make_float4(pj.x, pj.y, vx, vy);
                s_inv[pos] = __fdividef(1.0f, vn);
            } else {
                s_ovf[pos - NCAP] = (unsigned short)s;
            }
        }
    }
    __syncthreads();

    // ---------------- Phase 2: stream candidates ----------------
    const int len = s_cnt;
    const int n1  = (len < NCAP) ? len : NCAP;
    float m0 = FINF, m1 = FINF;

#define EVAL(J, M)                                                  \
    {                                                               \
        const float4 q = s_seg[J]; const float inv = s_inv[J];      \
        const float ux = gx - q.x, uy = gy - q.y;                   \
        const float uv = fmaf(ux, q.z, uy * q.w);                   \
        const float t  = satmul(uv, inv);                           \
        const float dx = fmaf(-t, q.z, ux);                         \
        const float dy = fmaf(-t, q.w, uy);                         \
        M = fminf(M, fmaf(dy, dy, dx * dx));                        \
    }

    int j = h;
    for (; j + 8 < n1; j += 16) {
        EVAL(j, m0)
        EVAL(j + 8, m1)
    }
    for (; j < n1; j += 8) {
        EVAL(j, m0)
    }

    // cold overflow path (len > NCAP; not hit on this data, exact if hit)
    if (len > NCAP) {
        const int novf = len - NCAP;
        for (int o2 = 0; o2 < novf; ++o2) {
            const int s = s_ovf[o2];
            const float2 pi = s_pt[s];
            const float2 pj = s_pt[s + 1];
            const float vx = pi.x - pj.x, vy = pi.y - pj.y;
            const float vn = vx * vx + vy * vy;
            const float inv = __fdividef(1.0f, vn);
            const float ux = gx - pj.x, uy = gy - pj.y;
            const float uv = fmaf(ux, vx, uy * vy);
            const float t  = satmul(uv, inv);
            const float dx = fmaf(-t, vx, ux);
            const float dy = fmaf(-t, vy, uy);
            m0 = fminf(m0, fmaf(dy, dy, dx * dx));
        }
    }

    s_m[p][h] = fminf(m0, m1);
    __syncthreads();

    // ---------------- Merge slices, publish mins, pair up ----------------
    const int pixbase = (ty * 4) * 128 + tx * 8;
    float qown = 0.0f;
    if (tid < 32) {
        const float* arr = s_m[p];
        qown = fminf(fminf(fminf(arr[0], arr[1]), fminf(arr[2], arr[3])),
                     fminf(fminf(arr[4], arr[5]), fminf(arr[6], arr[7])));
        g_pix[w][pixbase + row * 128 + col] = qown;
    }
    __threadfence();
    if (tid == 0) {
        const int old = atomicAdd(&g_tile_cnt[tile], 1);
        s_flag = (old == 1);
    }
    __syncthreads();

    // ---------------- Second arriver: tile loss partial ----------------
    if (s_flag) {
        float v = 0.0f;
        if (tid < 32) {
            const float qoth = g_pix[w ^ 1][pixbase + row * 128 + col];
            const float bo = expf(-GAMMA_F * qown);
            const float bt = expf(-GAMMA_F * qoth);
            const float d  = bo - bt;
            v = d * d;
#pragma unroll
            for (int o = 16; o > 0; o >>= 1)
                v += __shfl_xor_sync(0xFFFFFFFFu, v, o);
        }
        if (tid == 0) {
            atomicAdd(&g_loss, v);
            __threadfence();
            const unsigned old2 = atomicAdd(&g_done, 1u);
            s_flag = (old2 == NTILE - 1) ? 2 : 0;
        }
        __syncthreads();

        // ---------------- Last loss-CTA: finalize + reset ----------------
        if (s_flag == 2) {
            for (int i = tid; i < NTILE; i += 256) g_tile_cnt[i] = 0;
            if (tid == 0) {
                const float total = *((volatile float*)&g_loss);
                out[0] = total * (1.0f / (float)NPIX);
                g_loss = 0.0f;
                g_done = 0u;
            }
        }
    }
}

// ---------------------------------------------------------------------------
extern "C" void kernel_launch(void* const* d_in, const int* in_sizes, int n_in,
                              void* d_out, int out_size) {
    const float* pred = (const float*)d_in[0];
    const float* gt   = (const float*)d_in[1];
    float* out = (float*)d_out;

    fused_kernel<<<1024, 256>>>(pred, gt, out);
}

// round 9
// speedup vs baseline: 1.2000x; 1.2000x over previous
#include <cuda_runtime.h>
#include <math.h>

#define NSEG    2047
#define NPIX    16384
#define NTILE   512          // 16 x-tiles (8px) * 32 y-tiles (4px)
#define NCAP    768          // smem candidate capacity
#define GAMMA_F 200.0f
#define STEPF   (2.0f / 127.0f)
// tile = 8x4 px, center (+3.5,+1.5): 2*half-diag = 2*sqrt(3.5^2+1.5^2) px
#define THR_ADD (7.615773f * STEPF + 1e-3f)
#define FINF    __int_as_float(0x7F800000)

__device__ __forceinline__ float satmul(float a, float b) {
    float r; asm("mul.rn.sat.f32 %0,%1,%2;" : "=f"(r) : "f"(a), "f"(b)); return r;
}

// Cross-CTA state, reset by the last loss-CTA every run (graph-replay safe).
__device__ float    g_pix[2][NPIX];
__device__ int      g_tile_cnt[NTILE];
__device__ float    g_loss = 0.0f;
__device__ unsigned g_done = 0;

// ---------------------------------------------------------------------------
// grid 1024 x 128: bid = w*512 + tile (8x4 px).
// Phase 1: thread owns 16 CONTIGUOUS segments [16*tid, 16*tid+16): loads its
//          17 points as 13 coalesced LDG.128 into registers, converts and
//          evals at tile center from registers (no LDS, no scattered loads).
//          Block-min U -> exact triangle-inequality cull; survivors written
//          to s_seg/s_inv DIRECTLY FROM REGISTERS.
// Phase 2: thread = (pixel p=tid&31, slice h=tid>>5 of 4); streams s_seg
//          (warp-broadcast LDS), 2 accumulator chains.
// Pairing: g_pix publish, second arriver computes tile loss, 512th loss-CTA
//          writes out[0] and resets counters.
// ---------------------------------------------------------------------------
__global__ void __launch_bounds__(128) fused_kernel(const float* __restrict__ pred,
                                                    const float* __restrict__ gt,
                                                    float* __restrict__ out) {
    const int tid  = threadIdx.x;
    const int bid  = blockIdx.x;
    const int w    = bid >> 9;
    const int tile = bid & (NTILE - 1);
    const int tx = tile & 15, ty = tile >> 4;

    const float* __restrict__ c = w ? gt : pred;

    const float cx = fmaf((float)(tx * 8) + 3.5f, STEPF, -1.0f);
    const float cy = fmaf((float)(ty * 4) + 1.5f, STEPF, -1.0f);

    const int p = tid & 31, h = tid >> 5;        // pixel, slice (4 warps)
    const int row = p >> 3, col = p & 7;
    const float gx = fmaf((float)(tx * 8 + col), STEPF, -1.0f);
    const float gy = fmaf((float)(ty * 4 + row), STEPF, -1.0f);

    __shared__ float4 s_seg[NCAP];                      // 12 KB
    __shared__ float  s_inv[NCAP];                      //  3 KB
    __shared__ unsigned short s_ovf[NSEG - NCAP + 1];   // ~2.6 KB cold
    __shared__ float  s_m[32][4];
    __shared__ float  s_red[4];
    __shared__ int    s_cnt;
    __shared__ int    s_flag;

    if (tid == 0) s_cnt = 0;

    // ---- Phase 1a: coalesced register staging of this thread's 17 points ----
    // floats [48*tid, 48*tid+52) ; clamp last vector (seg 2047 is guarded out)
    const float4* __restrict__ c4 = (const float4*)c;
    float f[52];
#pragma unroll
    for (int q = 0; q < 13; ++q) {
        int idx = 12 * tid + q;
        if (idx > 1535) idx = 1535;            // only affects tid=127 tail
        const float4 v4 = __ldg(&c4[idx]);
        f[q * 4 + 0] = v4.x; f[q * 4 + 1] = v4.y;
        f[q * 4 + 2] = v4.z; f[q * 4 + 3] = v4.w;
    }

    // ---- Phase 1b: center eval from registers ----
    float d2c[16];
    float lmin = FINF;
#pragma unroll
    for (int k = 0; k < 16; ++k) {
        const int s = 16 * tid + k;
        float d2 = FINF;
        const float pen = f[k * 3 + 2];
        const bool masked = w ? (pen != 0.0f) : (pen > 0.5f);
        if (s < NSEG && !masked) {
            const float pjx = fmaf(f[k * 3 + 3], 2.0f, -1.0f);
            const float pjy = fmaf(f[k * 3 + 4], 2.0f, -1.0f);
            const float vx  = fmaf(f[k * 3 + 0], 2.0f, -1.0f) - pjx;
            const float vy  = fmaf(f[k * 3 + 1], 2.0f, -1.0f) - pjy;
            const float vn  = vx * vx + vy * vy;
            const float inv = __fdividef(1.0f, vn);   // vn=0 -> inf; sat(NaN)=0 -> t=0 (exact)
            const float ux = cx - pjx, uy = cy - pjy;
            const float uv = fmaf(ux, vx, uy * vy);
            const float t  = satmul(uv, inv);
            const float dx = fmaf(-t, vx, ux);
            const float dy = fmaf(-t, vy, uy);
            d2 = fmaf(dy, dy, dx * dx);
        }
        d2c[k] = d2;
        lmin = fminf(lmin, d2);
    }
#pragma unroll
    for (int o = 16; o > 0; o >>= 1)
        lmin = fminf(lmin, __shfl_xor_sync(0xFFFFFFFFu, lmin, o));
    if ((tid & 31) == 0) s_red[tid >> 5] = lmin;
    __syncthreads();
    const float U   = fminf(fminf(s_red[0], s_red[1]), fminf(s_red[2], s_red[3]));
    const float thd = sqrtf(U) + THR_ADD;
    const float thr = thd * thd;

    // ---- Phase 1c: survivors -> smem, straight from registers ----
#pragma unroll
    for (int k = 0; k < 16; ++k) {
        if (d2c[k] < thr) {
            const int pos = atomicAdd(&s_cnt, 1);
            if (pos < NCAP) {
                const float pjx = fmaf(f[k * 3 + 3], 2.0f, -1.0f);
                const float pjy = fmaf(f[k * 3 + 4], 2.0f, -1.0f);
                const float vx  = fmaf(f[k * 3 + 0], 2.0f, -1.0f) - pjx;
                const float vy  = fmaf(f[k * 3 + 1], 2.0f, -1.0f) - pjy;
                const float vn  = vx * vx + vy * vy;
                s_seg[pos] = make_float4(pjx, pjy, vx, vy);
                s_inv[pos] = __fdividef(1.0f, vn);
            } else {
                s_ovf[pos - NCAP] = (unsigned short)(16 * tid + k);
            }
        }
    }
    __syncthreads();

    // ---------------- Phase 2: stream candidates ----------------
    const int len = s_cnt;
    const int n1  = (len < NCAP) ? len : NCAP;
    float m0 = FINF, m1 = FINF;

#define EVAL(J, M)                                                  \
    {                                                               \
        const float4 q = s_seg[J]; const float inv = s_inv[J];      \
        const float ux = gx - q.x, uy = gy - q.y;                   \
        const float uv = fmaf(ux, q.z, uy * q.w);                   \
        const float t  = satmul(uv, inv);                           \
        const float dx = fmaf(-t, q.z, ux);                         \
        const float dy = fmaf(-t, q.w, uy);                         \
        M = fminf(M, fmaf(dy, dy, dx * dx));                        \
    }

    int j = h;
    for (; j + 4 < n1; j += 8) {
        EVAL(j, m0)
        EVAL(j + 4, m1)
    }
    for (; j < n1; j += 4) {
        EVAL(j, m0)
    }

    // cold overflow path (len > NCAP; not hit on this data, exact if hit)
    if (len > NCAP) {
        const int novf = len - NCAP;
        for (int o2 = 0; o2 < novf; ++o2) {
            const int s = s_ovf[o2];
            const float pjx = fmaf(__ldg(&c[s * 3 + 3]), 2.0f, -1.0f);
            const float pjy = fmaf(__ldg(&c[s * 3 + 4]), 2.0f, -1.0f);
            const float vx  = fmaf(__ldg(&c[s * 3 + 0]), 2.0f, -1.0f) - pjx;
            const float vy  = fmaf(__ldg(&c[s * 3 + 1]), 2.0f, -1.0f) - pjy;
            const float vn  = vx * vx + vy * vy;
            const float inv = __fdividef(1.0f, vn);
            const float ux = gx - pjx, uy = gy - pjy;
            const float uv = fmaf(ux, vx, uy * vy);
            const float t  = satmul(uv, inv);
            const float dx = fmaf(-t, vx, ux);
            const float dy = fmaf(-t, vy, uy);
            m0 = fminf(m0, fmaf(dy, dy, dx * dx));
        }
    }

    s_m[p][h] = fminf(m0, m1);
    __syncthreads();

    // ---------------- Merge slices, publish mins, pair up ----------------
    const int pixbase = (ty * 4) * 128 + tx * 8;
    float qown = 0.0f;
    if (tid < 32) {
        qown = fminf(fminf(s_m[p][0], s_m[p][1]), fminf(s_m[p][2], s_m[p][3]));
        g_pix[w][pixbase + row * 128 + col] = qown;
    }
    __threadfence();
    if (tid == 0) {
        const int old = atomicAdd(&g_tile_cnt[tile], 1);
        s_flag = (old == 1);
    }
    __syncthreads();

    // ---------------- Second arriver: tile loss partial ----------------
    if (s_flag) {
        float v = 0.0f;
        if (tid < 32) {
            const float qoth = g_pix[w ^ 1][pixbase + row * 128 + col];
            const float bo = expf(-GAMMA_F * qown);
            const float bt = expf(-GAMMA_F * qoth);
            const float d  = bo - bt;
            v = d * d;
#pragma unroll
            for (int o = 16; o > 0; o >>= 1)
                v += __shfl_xor_sync(0xFFFFFFFFu, v, o);
        }
        if (tid == 0) {
            atomicAdd(&g_loss, v);
            __threadfence();
            const unsigned old2 = atomicAdd(&g_done, 1u);
            s_flag = (old2 == NTILE - 1) ? 2 : 0;
        }
        __syncthreads();

        // ---------------- Last loss-CTA: finalize + reset ----------------
        if (s_flag == 2) {
            for (int i = tid; i < NTILE; i += 128) g_tile_cnt[i] = 0;
            if (tid == 0) {
                const float total = *((volatile float*)&g_loss);
                out[0] = total * (1.0f / (float)NPIX);
                g_loss = 0.0f;
                g_done = 0u;
            }
        }
    }
}

// ---------------------------------------------------------------------------
extern "C" void kernel_launch(void* const* d_in, const int* in_sizes, int n_in,
                              void* d_out, int out_size) {
    const float* pred = (const float*)d_in[0];
    const float* gt   = (const float*)d_in[1];
    float* out = (float*)d_out;

    fused_kernel<<<1024, 128>>>(pred, gt, out);
}

// round 10
// speedup vs baseline: 1.5551x; 1.2959x over previous
#include <cuda_runtime.h>
#include <math.h>

#define NSEG    2047
#define NPIX    16384
#define NTILE   256          // 16 x 16 tiles of 8x8 px
#define NCAP    768          // smem candidate capacity (padded to mult of 32)
#define GAMMA4  800.0f       // gamma * 4 (raw-space d^2 = true d^2 / 4)
#define STEPR   (1.0f / 127.0f)            // raw-space grid step
// tile = 8x8 px, center (+3.5,+3.5): 2*half-diag = 7*sqrt(2) px (raw units)
#define THR_ADD (9.899495f * STEPR + 5e-4f)
#define FINF    __int_as_float(0x7F800000)

__device__ __forceinline__ float satmul(float a, float b) {
    float r; asm("mul.rn.sat.f32 %0,%1,%2;" : "=f"(r) : "f"(a), "f"(b)); return r;
}

// Cross-CTA state, reset by the last loss-CTA every run (graph-replay safe).
__device__ float    g_pix[2][NPIX];   // raw-space per-pixel min d^2
__device__ int      g_tile_cnt[NTILE];
__device__ float    g_loss = 0.0f;
__device__ unsigned g_done = 0;

// ---------------------------------------------------------------------------
// grid 512 x 256: bid = w*256 + tile (8x8 px). ALL math in RAW [0,1] space.
// Phase 1: thread owns 8 contiguous segments; 7 coalesced LDG.128 stage its
//          28 floats; center eval from registers; block-min U; exact
//          triangle-inequality cull; survivors -> s_seg/s_inv from registers;
//          list padded to multiple of 32 with far dummies.
// Phase 2: warp = pixel row (8 rows), lane = candidate slice (32); thread
//          evaluates its whole 8-px row per candidate (uy shared); merge by
//          warp shuffle-min.
// Pairing: publish 64 mins to g_pix; second arriver computes tile loss with
//          beta = exp(-800 * d2_raw); 256th loss-CTA writes out[0], resets.
// ---------------------------------------------------------------------------
__global__ void __launch_bounds__(256, 3) fused_kernel(const float* __restrict__ pred,
                                                       const float* __restrict__ gt,
                                                       float* __restrict__ out) {
    const int tid  = threadIdx.x;
    const int bid  = blockIdx.x;
    const int w    = bid >> 8;
    const int tile = bid & (NTILE - 1);
    const int tx = tile & 15, ty = tile >> 4;

    const float* __restrict__ c = w ? gt : pred;

    const float cxr = ((float)(tx * 8) + 3.5f) * STEPR;   // raw-space center
    const float cyr = ((float)(ty * 8) + 3.5f) * STEPR;

    const int rowi = tid >> 5;          // warp = pixel row 0..7
    const int h    = tid & 31;          // lane = candidate slice
    const float gyr = (float)(ty * 8 + rowi) * STEPR;

    __shared__ float4 s_seg[NCAP];                      // 12 KB
    __shared__ float  s_inv[NCAP];                      //  3 KB
    __shared__ unsigned short s_ovf[NSEG - NCAP + 1];   // ~2.6 KB cold
    __shared__ float  s_q[64];
    __shared__ float  s_red[8];
    __shared__ int    s_cnt;
    __shared__ int    s_flag;

    if (tid == 0) s_cnt = 0;

    // ---- Phase 1a: stage 28 floats (points 8t..8t+9) via 7 LDG.128 ----
    const float4* __restrict__ c4 = (const float4*)c;
    float f[28];
#pragma unroll
    for (int q = 0; q < 7; ++q) {
        int idx = 6 * tid + q;
        if (idx > 1535) idx = 1535;     // tail clamp; only affects guarded seg 2047
        const float4 v4 = __ldg(&c4[idx]);
        f[q * 4 + 0] = v4.x; f[q * 4 + 1] = v4.y;
        f[q * 4 + 2] = v4.z; f[q * 4 + 3] = v4.w;
    }

    // ---- Phase 1b: center eval in raw space ----
    float d2c[8];
    float lmin = FINF;
#pragma unroll
    for (int k = 0; k < 8; ++k) {
        const int s = 8 * tid + k;
        float d2 = FINF;
        const float pen = f[k * 3 + 2];
        const bool masked = w ? (pen != 0.0f) : (pen > 0.5f);
        if (s < NSEG && !masked) {
            const float pjx = f[k * 3 + 3];
            const float pjy = f[k * 3 + 4];
            const float vx  = f[k * 3 + 0] - pjx;
            const float vy  = f[k * 3 + 1] - pjy;
            const float vn  = vx * vx + vy * vy;
            const float inv = __fdividef(1.0f, vn);  // vn=0 -> inf; sat(NaN)=0 -> t=0 exact
            const float ux = cxr - pjx, uy = cyr - pjy;
            const float uv = fmaf(ux, vx, uy * vy);
            const float t  = satmul(uv, inv);
            const float dx = fmaf(-t, vx, ux);
            const float dy = fmaf(-t, vy, uy);
            d2 = fmaf(dy, dy, dx * dx);
        }
        d2c[k] = d2;
        lmin = fminf(lmin, d2);
    }
#pragma unroll
    for (int o = 16; o > 0; o >>= 1)
        lmin = fminf(lmin, __shfl_xor_sync(0xFFFFFFFFu, lmin, o));
    if (h == 0) s_red[rowi] = lmin;
    __syncthreads();
    float U = s_red[0];
#pragma unroll
    for (int q = 1; q < 8; ++q) U = fminf(U, s_red[q]);
    const float thd = sqrtf(U) + THR_ADD;
    const float thr = thd * thd;

    // ---- Phase 1c: survivors -> smem straight from registers ----
#pragma unroll
    for (int k = 0; k < 8; ++k) {
        if (d2c[k] < thr) {
            const int pos = atomicAdd(&s_cnt, 1);
            if (pos < NCAP) {
                const float pjx = f[k * 3 + 3];
                const float pjy = f[k * 3 + 4];
                const float vx  = f[k * 3 + 0] - pjx;
                const float vy  = f[k * 3 + 1] - pjy;
                const float vn  = vx * vx + vy * vy;
                s_seg[pos] = make_float4(pjx, pjy, vx, vy);
                s_inv[pos] = __fdividef(1.0f, vn);
            } else {
                s_ovf[pos - NCAP] = (unsigned short)(8 * tid + k);
            }
        }
    }
    __syncthreads();

    // pad candidate list to a multiple of 32 with far dummies (no tail guard)
    const int len  = s_cnt;
    const int n1   = (len < NCAP) ? len : NCAP;
    const int npad = (n1 + 31) & ~31;
    if (tid < npad - n1) {
        s_seg[n1 + tid] = make_float4(1e9f, 1e9f, 0.0f, 0.0f);
        s_inv[n1 + tid] = 0.0f;
    }
    __syncthreads();

    // ---- Phase 2: warp=row, lane=slice; 8 px per thread per candidate ----
    float gxr[8], m[8];
#pragma unroll
    for (int k = 0; k < 8; ++k) {
        gxr[k] = (float)(tx * 8 + k) * STEPR;
        m[k]   = FINF;
    }

    for (int j = h; j < npad; j += 32) {
        const float4 q  = s_seg[j];
        const float inv = s_inv[j];
        const float uy  = gyr - q.y;
        const float cyv = uy * q.w;
#pragma unroll
        for (int k = 0; k < 8; ++k) {
            const float ux = gxr[k] - q.x;
            const float uv = fmaf(ux, q.z, cyv);
            const float t  = satmul(uv, inv);
            const float dx = fmaf(-t, q.z, ux);
            const float dy = fmaf(-t, q.w, uy);
            m[k] = fminf(m[k], fmaf(dy, dy, dx * dx));
        }
    }

    // cold overflow path (len > NCAP; not hit on this data, exact if hit)
    if (len > NCAP) {
        const int novf = len - NCAP;
        for (int o2 = 0; o2 < novf; ++o2) {
            const int s = s_ovf[o2];
            const float pjx = __ldg(&c[s * 3 + 3]);
            const float pjy = __ldg(&c[s * 3 + 4]);
            const float vx  = __ldg(&c[s * 3 + 0]) - pjx;
            const float vy  = __ldg(&c[s * 3 + 1]) - pjy;
            const float vn  = vx * vx + vy * vy;
            const float inv = __fdividef(1.0f, vn);
            const float uy  = gyr - pjy;
            const float cyv = uy * vy;
#pragma unroll
            for (int k = 0; k < 8; ++k) {
                const float ux = gxr[k] - pjx;
                const float uv = fmaf(ux, vx, cyv);
                const float t  = satmul(uv, inv);
                const float dx = fmaf(-t, vx, ux);
                const float dy = fmaf(-t, vy, uy);
                m[k] = fminf(m[k], fmaf(dy, dy, dx * dx));
            }
        }
    }

    // ---- warp shuffle-min across 32 slices, publish ----
#pragma unroll
    for (int o = 16; o > 0; o >>= 1) {
#pragma unroll
        for (int k = 0; k < 8; ++k)
            m[k] = fminf(m[k], __shfl_xor_sync(0xFFFFFFFFu, m[k], o));
    }
    const int pixbase = (ty * 8) * 128 + tx * 8;
    if (h < 8) {
        const float q = m[h];                 // pixel (rowi, h)
        s_q[rowi * 8 + h] = q;
        g_pix[w][pixbase + rowi * 128 + h] = q;
    }
    __threadfence();
    if (tid == 0) {
        const int old = atomicAdd(&g_tile_cnt[tile], 1);
        s_flag = (old == 1);
    }
    __syncthreads();

    // ---- second arriver: tile loss partial over 64 pixels ----
    if (s_flag) {
        float v = 0.0f;
        if (tid < 64) {
            const int rr = tid >> 3, cc = tid & 7;
            const float qown = s_q[tid];
            const float qoth = g_pix[w ^ 1][pixbase + rr * 128 + cc];
            const float bo = expf(-GAMMA4 * qown);
            const float bt = expf(-GAMMA4 * qoth);
            const float d  = bo - bt;
            v = d * d;
        }
#pragma unroll
        for (int o = 16; o > 0; o >>= 1)
            v += __shfl_xor_sync(0xFFFFFFFFu, v, o);
        if (tid == 0 || tid == 32) s_red[tid >> 5] = v;
        __syncthreads();
        if (tid == 0) {
            atomicAdd(&g_loss, s_red[0] + s_red[1]);
            __threadfence();
            const unsigned old2 = atomicAdd(&g_done, 1u);
            s_flag = (old2 == NTILE - 1) ? 2 : 0;
        }
        __syncthreads();

        // ---- last loss-CTA: finalize + reset ----
        if (s_flag == 2) {
            if (tid < NTILE) g_tile_cnt[tid] = 0;
            if (tid == 0) {
                const float total = *((volatile float*)&g_loss);
                out[0] = total * (1.0f / (float)NPIX);
                g_loss = 0.0f;
                g_done = 0u;
            }
        }
    }
}

// ---------------------------------------------------------------------------
extern "C" void kernel_launch(void* const* d_in, const int* in_sizes, int n_in,
                              void* d_out, int out_size) {
    const float* pred = (const float*)d_in[0];
    const float* gt   = (const float*)d_in[1];
    float* out = (float*)d_out;

    fused_kernel<<<512, 256>>>(pred, gt, out);
}